// round 4
// baseline (speedup 1.0000x reference)
#include <cuda_runtime.h>
#include <cstdint>

// RWKV WKV recurrence, B=16, T=2048, D=1024 fp32.
//   a_t = exp(w_t)*a_{t-1} + exp(k_t)
//   b_t = exp(w_t)*b_{t-1} + exp(k_t)*v_t ;  out_t = b_t / a_t
//
// Warp-specialized single kernel per SM:
//   warps 0-3 : consumers, one thread per (batch,d) channel (128 channels/block)
//   warp 4    : producer, fills an 8-stage SMEM ring via cp.async.bulk
//               (bulk async engine -> no per-warp LDG in-flight cap)
// Synchronization is purely mbarrier full/empty pairs; no __syncthreads in
// the steady-state loop (each consumer thread reads only its own column).

#define TT   2048
#define DD   1024
#define UU   16                       // timesteps per stage
#define NST  8                        // ring depth
#define CH   128                      // channels per block
#define TOTAL_STAGES (TT / UU)        // 128
#define STAGE_FLOATS (3 * UU * CH)    // 6144
#define STAGE_BYTES  (STAGE_FLOATS * 4)  // 24576
#define BAR_OFF (NST * STAGE_FLOATS)  // float-index of barrier region

extern __shared__ float smbuf[];

__device__ __forceinline__ uint32_t s2u(const void* p) {
    return (uint32_t)__cvta_generic_to_shared(p);
}
__device__ __forceinline__ void mbar_init(uint32_t a, uint32_t cnt) {
    asm volatile("mbarrier.init.shared.b64 [%0], %1;" :: "r"(a), "r"(cnt) : "memory");
}
__device__ __forceinline__ void mbar_expect_tx(uint32_t a, uint32_t bytes) {
    asm volatile("mbarrier.arrive.expect_tx.shared.b64 _, [%0], %1;"
                 :: "r"(a), "r"(bytes) : "memory");
}
__device__ __forceinline__ void mbar_arrive(uint32_t a) {
    asm volatile("mbarrier.arrive.shared.b64 _, [%0];" :: "r"(a) : "memory");
}
__device__ __forceinline__ void mbar_wait(uint32_t a, uint32_t ph) {
    uint32_t done;
    asm volatile("{\n\t.reg .pred p;\n\t"
                 "mbarrier.try_wait.parity.acquire.cta.shared::cta.b64 p, [%1], %2;\n\t"
                 "selp.b32 %0, 1, 0, p;\n\t}"
                 : "=r"(done) : "r"(a), "r"(ph) : "memory");
    if (!done) {
        asm volatile("{\n\t.reg .pred P1;\n\t"
                     "W_%=:\n\t"
                     "mbarrier.try_wait.parity.acquire.cta.shared::cta.b64 P1, [%0], %1, 0x989680;\n\t"
                     "@P1 bra.uni D_%=;\n\t"
                     "bra.uni W_%=;\n\t"
                     "D_%=:\n\t}"
                     :: "r"(a), "r"(ph) : "memory");
    }
}
__device__ __forceinline__ void bulk_g2s(uint32_t dst, const void* src,
                                         uint32_t bytes, uint32_t bar) {
    asm volatile("cp.async.bulk.shared::cta.global.mbarrier::complete_tx::bytes "
                 "[%0], [%1], %2, [%3];"
                 :: "r"(dst), "l"(src), "r"(bytes), "r"(bar) : "memory");
}

__global__ void __launch_bounds__(160, 1)
wkv_kernel(const float* __restrict__ k,
           const float* __restrict__ v,
           const float* __restrict__ w,
           float* __restrict__ out)
{
    const int tid = threadIdx.x;
    const int bi  = blockIdx.x >> 3;          // batch index (8 blocks/batch)
    const int d0  = (blockIdx.x & 7) * CH;    // channel base within D
    const long base = (long)bi * TT * DD + d0;

    const uint32_t bar_base = s2u(&smbuf[BAR_OFF]);
    // interleaved [full0, empty0, full1, empty1, ...]
#define FULLB(s)  (bar_base + (uint32_t)(s) * 16u)
#define EMPTYB(s) (bar_base + (uint32_t)(s) * 16u + 8u)

    if (tid == 0) {
        for (int i = 0; i < NST; i++) {
            mbar_init(FULLB(i), 1);      // producer's arrive.expect_tx
            mbar_init(EMPTYB(i), CH);    // 128 consumer arrivals
        }
    }
    asm volatile("fence.proxy.async.shared::cta;" ::: "memory");
    __syncthreads();

    if (tid >= CH) {
        // ---------------- producer warp ----------------
        const int lane = tid - CH;
        const float* srcs0 = k + base;
        const float* srcs1 = v + base;
        const float* srcs2 = w + base;
        for (int s = 0; s < TOTAL_STAGES; s++) {
            const int slot   = s & (NST - 1);
            const uint32_t ph = ((s >> 3) & 1u) ^ 1u;   // producer starts phase 1
            mbar_wait(EMPTYB(slot), ph);
            if (lane == 0) mbar_expect_tx(FULLB(slot), STAGE_BYTES);
            __syncwarp();
            // 48 rows (3 tensors x UU steps), 512B each
            for (int j = lane; j < 3 * UU; j += 32) {
                const int tensor = j >> 4;
                const int i      = j & (UU - 1);
                const float* src = (tensor == 0 ? srcs0 : (tensor == 1 ? srcs1 : srcs2))
                                   + (long)(s * UU + i) * DD;
                const uint32_t dst =
                    s2u(&smbuf[((slot * 3 + tensor) * UU + i) * CH]);
                bulk_g2s(dst, src, CH * 4, FULLB(slot));
            }
        }
    } else {
        // ---------------- consumer threads (one per channel) ----------------
        float a = 0.0f, b = 0.0f;
        float* go = out + base + tid;
        for (int s = 0; s < TOTAL_STAGES; s++) {
            const int slot    = s & (NST - 1);
            const uint32_t ph = (s >> 3) & 1u;
            mbar_wait(FULLB(slot), ph);

            const float* sk = &smbuf[(slot * 3 + 0) * UU * CH + tid];
            const float* sv = &smbuf[(slot * 3 + 1) * UU * CH + tid];
            const float* sw = &smbuf[(slot * 3 + 2) * UU * CH + tid];
            float* o = go + (long)s * UU * DD;
#pragma unroll
            for (int i = 0; i < UU; i++) {
                const float ew = __expf(sw[i * CH]);
                const float ek = __expf(sk[i * CH]);
                a = fmaf(ew, a, ek);
                b = fmaf(ew, b, ek * sv[i * CH]);
                o[(long)i * DD] = __fdividef(b, a);
            }
            mbar_arrive(EMPTYB(slot));
        }
    }
#undef FULLB
#undef EMPTYB
}

extern "C" void kernel_launch(void* const* d_in, const int* in_sizes, int n_in,
                              void* d_out, int out_size)
{
    const float* k = (const float*)d_in[0];
    const float* v = (const float*)d_in[1];
    const float* w = (const float*)d_in[2];
    float* out = (float*)d_out;

    const int smem_bytes = NST * STAGE_BYTES + NST * 16;   // stages + barriers
    cudaFuncSetAttribute(wkv_kernel,
                         cudaFuncAttributeMaxDynamicSharedMemorySize, smem_bytes);

    // 16384 channels / 128 consumers per block = 128 blocks, one per SM.
    wkv_kernel<<<128, 160, smem_bytes>>>(k, v, w, out);
}

// round 6
// speedup vs baseline: 1.4218x; 1.4218x over previous
#include <cuda_runtime.h>

// RWKV WKV recurrence, B=16, T=2048, D=1024 fp32.
//   a_t = exp(w_t)*a_{t-1} + exp(k_t)
//   b_t = exp(w_t)*b_{t-1} + exp(k_t)*v_t ;  out_t = b_t / a_t
//
// One thread per (batch,d) channel, sequential in t. Rolling register
// prefetch: 16-deep circular buffer, each step computes slot i then reloads
// it for step i+16. In-flight LDGs per warp stay pinned at ~48 (vs the
// oscillating 48->0 of a block double-buffer), keeping chip-wide in-flight
// bytes above the HBM bandwidth-delay product continuously.

#define TT 2048
#define DD 1024
#define PF 16            // prefetch distance / buffer depth; 3*PF=48 LDG in flight

__global__ void __launch_bounds__(128, 1)
wkv_kernel(const float* __restrict__ k,
           const float* __restrict__ v,
           const float* __restrict__ w,
           float* __restrict__ out)
{
    const int c  = blockIdx.x * blockDim.x + threadIdx.x;  // 0 .. B*D-1
    const int bi = c >> 10;          // c / DD
    const int di = c & (DD - 1);     // c % DD
    const long base = (long)bi * TT * DD + di;

    const float* kp = k + base;
    const float* vp = v + base;
    const float* wp = w + base;
    float*       op = out + base;

    float kb[PF], vb[PF], wb[PF];

    // Prologue: fill the buffer with steps 0..PF-1.
#pragma unroll
    for (int i = 0; i < PF; i++) {
        kb[i] = __ldcs(kp + i * DD);
        vb[i] = __ldcs(vp + i * DD);
        wb[i] = __ldcs(wp + i * DD);
    }
    kp += PF * DD; vp += PF * DD; wp += PF * DD;

    float a = 0.0f, b = 0.0f;

    // Steady state: compute step t0+i from slot i, then refill slot i with
    // step t0+i+PF. The WAR on the buffer register forces the reload to
    // stay after the consume, pinning in-flight loads at ~3*PF per warp.
    for (int t0 = 0; t0 < TT - PF; t0 += PF) {
#pragma unroll
        for (int i = 0; i < PF; i++) {
            const float ew = __expf(wb[i]);
            const float ek = __expf(kb[i]);
            a = fmaf(ew, a, ek);
            b = fmaf(ew, b, ek * vb[i]);
            __stcs(op + i * DD, __fdividef(b, a));

            kb[i] = __ldcs(kp + i * DD);
            vb[i] = __ldcs(vp + i * DD);
            wb[i] = __ldcs(wp + i * DD);
        }
        kp += PF * DD; vp += PF * DD; wp += PF * DD; op += PF * DD;
    }

    // Epilogue: last PF steps, no reload.
#pragma unroll
    for (int i = 0; i < PF; i++) {
        const float ew = __expf(wb[i]);
        const float ek = __expf(kb[i]);
        a = fmaf(ew, a, ek);
        b = fmaf(ew, b, ek * vb[i]);
        __stcs(op + i * DD, __fdividef(b, a));
    }
}

extern "C" void kernel_launch(void* const* d_in, const int* in_sizes, int n_in,
                              void* d_out, int out_size)
{
    const float* k = (const float*)d_in[0];
    const float* v = (const float*)d_in[1];
    const float* w = (const float*)d_in[2];
    float* out = (float*)d_out;

    // 16384 channels / 128 threads = 128 blocks, one per SM, balanced.
    wkv_kernel<<<128, 128>>>(k, v, w, out);
}